// round 13
// baseline (speedup 1.0000x reference)
#include <cuda_runtime.h>
#include <cuda_fp16.h>
#include <math.h>
#include <stdint.h>

// ---------------- problem constants ----------------
#define BATCH   4
#define NTOK    1024
#define EMBED   768
#define HEADS   12
#define HD      64
#define DEPTH   4
#define QKVC    2304
#define MLPD    3072
#define MTOT    4096
#define BH      48
#define RELT    63

// ---------------- scratch ----------------
__device__ float g_h[MTOT * EMBED];
__device__ float g_ln[MTOT * EMBED];
__device__ float g_qkv[MTOT * QKVC];
__device__ float g_attnout[MTOT * EMBED];
__device__ float g_mlp[MTOT * MLPD];
__device__ float g_relh[BH * NTOK * 32];
__device__ float g_relw[BH * NTOK * 32];
__device__ float g_col[MTOT * EMBED];
__device__ float g_wt[EMBED * EMBED];

// ---------------- helpers ----------------
__device__ __forceinline__ float gelu_exact(float x) {
    return 0.5f * x * (1.0f + erff(x * 0.70710678118654752440f));
}
__device__ __forceinline__ float blockSum256(float v, float* red) {
    const int tid = threadIdx.x;
    #pragma unroll
    for (int o = 16; o > 0; o >>= 1) v += __shfl_xor_sync(0xffffffffu, v, o);
    if ((tid & 31) == 0) red[tid >> 5] = v;
    __syncthreads();
    float t = 0.f;
    #pragma unroll
    for (int i = 0; i < 8; i++) t += red[i];
    return t;
}
__device__ __forceinline__ uint32_t h2_u32(__half2 h) {
    uint32_t u;
    *reinterpret_cast<__half2*>(&u) = h;
    return u;
}
__device__ __forceinline__ void mma_f16k8(float* d, uint32_t a0, uint32_t a1,
                                          uint32_t b0) {
    asm volatile(
        "mma.sync.aligned.m16n8k8.row.col.f32.f16.f16.f32 "
        "{%0,%1,%2,%3}, {%4,%5}, {%6}, {%0,%1,%2,%3};\n"
        : "+f"(d[0]), "+f"(d[1]), "+f"(d[2]), "+f"(d[3])
        : "r"(a0), "r"(a1), "r"(b0));
}
__device__ __forceinline__ void ldsm_x4_trans(uint32_t* r, uint32_t addr) {
    asm volatile(
        "ldmatrix.sync.aligned.m8n8.x4.trans.shared.b16 {%0,%1,%2,%3}, [%4];"
        : "=r"(r[0]), "=r"(r[1]), "=r"(r[2]), "=r"(r[3]) : "r"(addr));
}
__device__ __forceinline__ uint32_t smem_u32(const void* p) {
    uint32_t a;
    asm("{ .reg .u64 t; cvta.to.shared.u64 t, %1; cvt.u32.u64 %0, t; }"
        : "=r"(a) : "l"(p));
    return a;
}

// ---------------- fp16-frag GEMM, R11 structure, 128x128x16 tile -----------
// A[M,K] row-major f32, B[K,N] row-major f32; both converted to f16 at staging.
// As [m][k] stride 24, Bs [n][k] stride 24 (transposed at staging).
// EPI: 1 = +bias, 2 = +bias+res, 3 = gelu(+bias), 4 = +bias+pos
template <int EPI>
__global__ void __launch_bounds__(256) mma_gemm(
    int M, int N, int K,
    const float* __restrict__ A, const float* __restrict__ B,
    float* __restrict__ C,
    const float* __restrict__ bias, const float* __restrict__ res)
{
    constexpr int BM = 128, BN = 128, BK = 16, SK = 24;
    __shared__ __half As[2][BM][SK];
    __shared__ __half Bs[2][BN][SK];

    const int tid = threadIdx.x;
    const int lane = tid & 31;
    const int wid = tid >> 5;
    const int wm = wid & 1;
    const int wn = wid >> 1;
    const int g = lane >> 2, tg = lane & 3;

    const float* Ab = A + (size_t)blockIdx.y * BM * K;
    const float* Bb = B + blockIdx.x * BN;

    float acc[4][4][4];
    #pragma unroll
    for (int i = 0; i < 4; i++)
        #pragma unroll
        for (int j = 0; j < 4; j++)
            #pragma unroll
            for (int r = 0; r < 4; r++) acc[i][j][r] = 0.f;

    const int aRow0 = tid >> 2;          // 0..63 (+p*64)
    const int aC4   = tid & 3;           // k-chunk (4 floats)
    const int bRow0 = tid >> 5;          // 0..7  (+p*8)  (k index)
    const int bC4   = tid & 31;          // n-chunk (4 floats)

    float4 ra[2], rb[2];
    const int nIter = K / BK;

    #pragma unroll
    for (int p = 0; p < 2; p++) {
        ra[p] = *reinterpret_cast<const float4*>(
            Ab + (size_t)(aRow0 + p * 64) * K + aC4 * 4);
        rb[p] = *reinterpret_cast<const float4*>(
            Bb + (size_t)(bRow0 + p * 8) * N + bC4 * 4);
    }
    #pragma unroll
    for (int p = 0; p < 2; p++) {
        *reinterpret_cast<__half2*>(&As[0][aRow0 + p * 64][aC4 * 4]) =
            __floats2half2_rn(ra[p].x, ra[p].y);
        *reinterpret_cast<__half2*>(&As[0][aRow0 + p * 64][aC4 * 4 + 2]) =
            __floats2half2_rn(ra[p].z, ra[p].w);
        const int kk = bRow0 + p * 8;
        Bs[0][bC4 * 4 + 0][kk] = __float2half_rn(rb[p].x);
        Bs[0][bC4 * 4 + 1][kk] = __float2half_rn(rb[p].y);
        Bs[0][bC4 * 4 + 2][kk] = __float2half_rn(rb[p].z);
        Bs[0][bC4 * 4 + 3][kk] = __float2half_rn(rb[p].w);
    }
    __syncthreads();

    int buf = 0;
    for (int it = 0; it < nIter; ++it) {
        if (it + 1 < nIter) {
            const int k0 = (it + 1) * BK;
            #pragma unroll
            for (int p = 0; p < 2; p++) {
                ra[p] = *reinterpret_cast<const float4*>(
                    Ab + (size_t)(aRow0 + p * 64) * K + k0 + aC4 * 4);
                rb[p] = *reinterpret_cast<const float4*>(
                    Bb + (size_t)(k0 + bRow0 + p * 8) * N + bC4 * 4);
            }
        }
        #pragma unroll
        for (int kf = 0; kf < 2; kf++) {
            uint32_t af[4][2];
            uint32_t bf[4];
            #pragma unroll
            for (int mf = 0; mf < 4; mf++) {
                const int r = wm * 64 + mf * 16;
                af[mf][0] = *reinterpret_cast<const uint32_t*>(
                    &As[buf][r + g][kf * 8 + tg * 2]);
                af[mf][1] = *reinterpret_cast<const uint32_t*>(
                    &As[buf][r + 8 + g][kf * 8 + tg * 2]);
            }
            #pragma unroll
            for (int nf = 0; nf < 4; nf++) {
                const int c = wn * 32 + nf * 8;
                bf[nf] = *reinterpret_cast<const uint32_t*>(
                    &Bs[buf][c + g][kf * 8 + tg * 2]);
            }
            #pragma unroll
            for (int mf = 0; mf < 4; mf++)
                #pragma unroll
                for (int nf = 0; nf < 4; nf++)
                    mma_f16k8(acc[mf][nf], af[mf][0], af[mf][1], bf[nf]);
        }
        if (it + 1 < nIter) {
            #pragma unroll
            for (int p = 0; p < 2; p++) {
                *reinterpret_cast<__half2*>(&As[buf ^ 1][aRow0 + p * 64][aC4 * 4]) =
                    __floats2half2_rn(ra[p].x, ra[p].y);
                *reinterpret_cast<__half2*>(&As[buf ^ 1][aRow0 + p * 64][aC4 * 4 + 2]) =
                    __floats2half2_rn(ra[p].z, ra[p].w);
                const int kk = bRow0 + p * 8;
                Bs[buf ^ 1][bC4 * 4 + 0][kk] = __float2half_rn(rb[p].x);
                Bs[buf ^ 1][bC4 * 4 + 1][kk] = __float2half_rn(rb[p].y);
                Bs[buf ^ 1][bC4 * 4 + 2][kk] = __float2half_rn(rb[p].z);
                Bs[buf ^ 1][bC4 * 4 + 3][kk] = __float2half_rn(rb[p].w);
            }
        }
        __syncthreads();
        buf ^= 1;
    }

    #pragma unroll
    for (int mf = 0; mf < 4; mf++) {
        const int row0 = blockIdx.y * 128 + wm * 64 + mf * 16 + g;
        #pragma unroll
        for (int nf = 0; nf < 4; nf++) {
            const int col = blockIdx.x * 128 + wn * 32 + nf * 8 + tg * 2;
            #pragma unroll
            for (int half = 0; half < 2; half++) {
                const int m = row0 + half * 8;
                float c0 = acc[mf][nf][half * 2 + 0];
                float c1 = acc[mf][nf][half * 2 + 1];
                if (EPI == 1) {
                    c0 += bias[col]; c1 += bias[col + 1];
                } else if (EPI == 2) {
                    c0 += bias[col]     + res[(size_t)m * N + col];
                    c1 += bias[col + 1] + res[(size_t)m * N + col + 1];
                } else if (EPI == 3) {
                    c0 = gelu_exact(c0 + bias[col]);
                    c1 = gelu_exact(c1 + bias[col + 1]);
                } else if (EPI == 4) {
                    c0 += bias[col]     + res[(size_t)(m & (NTOK - 1)) * N + col];
                    c1 += bias[col + 1] + res[(size_t)(m & (NTOK - 1)) * N + col + 1];
                }
                *reinterpret_cast<float2*>(&C[(size_t)m * N + col]) =
                    make_float2(c0, c1);
            }
        }
    }
}

// ---------------- im2col ----------------
__global__ void __launch_bounds__(256) im2col_k(const float* __restrict__ x,
                                                float* __restrict__ col)
{
    int idx = blockIdx.x * 256 + threadIdx.x;
    int m = idx / EMBED, k = idx - m * EMBED;
    int b = m >> 10;
    int gy = (m >> 5) & 31, gx = m & 31;
    int ci = k >> 8;
    int ph = (k >> 4) & 15, pw = k & 15;
    col[idx] = x[(((size_t)b * 3 + ci) * 512 + gy * 16 + ph) * 512 + gx * 16 + pw];
}

__global__ void __launch_bounds__(256) transpose768_k(const float* __restrict__ w,
                                                      float* __restrict__ wt)
{
    int idx = blockIdx.x * 256 + threadIdx.x;
    int k = idx / EMBED, co = idx - k * EMBED;
    wt[idx] = w[(size_t)co * EMBED + k];
}

// ---------------- LayerNorm ----------------
__global__ void __launch_bounds__(256) layernorm_k(
    const float* __restrict__ in, const float* __restrict__ w,
    const float* __restrict__ b, float* __restrict__ out)
{
    __shared__ float red[8];
    const int tid = threadIdx.x;
    const float* p = in + (size_t)blockIdx.x * EMBED;
    float* q = out + (size_t)blockIdx.x * EMBED;
    float x0 = p[tid], x1 = p[tid + 256], x2 = p[tid + 512];
    float s  = blockSum256(x0 + x1 + x2, red);
    __syncthreads();
    float sq = blockSum256(x0 * x0 + x1 * x1 + x2 * x2, red);
    float mean = s * (1.f / 768.f);
    float var = sq * (1.f / 768.f) - mean * mean;
    float rs = rsqrtf(var + 1e-5f);
    q[tid]       = (x0 - mean) * rs * w[tid]       + b[tid];
    q[tid + 256] = (x1 - mean) * rs * w[tid + 256] + b[tid + 256];
    q[tid + 512] = (x2 - mean) * rs * w[tid + 512] + b[tid + 512];
}

// ---------------- rel-pos bias tables ----------------
__global__ void __launch_bounds__(64) rel_tables_k(
    const float* __restrict__ qkv, const float* __restrict__ rph,
    const float* __restrict__ rpw, float* __restrict__ relh,
    float* __restrict__ relw)
{
    __shared__ float qv[HD];
    const int bq = blockIdx.x;
    const int bh = bq >> 10, q = bq & 1023;
    const int b = bh / HEADS, head = bh % HEADS;
    const int hq = q >> 5, wq = q & 31;
    const int tid = threadIdx.x;
    qv[tid] = qkv[((size_t)(b * NTOK + q)) * QKVC + head * HD + tid];
    __syncthreads();
    const int kidx = tid & 31;
    const float* r;
    float* out;
    if (tid < 32) { r = rph + (hq - kidx + 31) * HD; out = relh; }
    else          { r = rpw + (wq - kidx + 31) * HD; out = relw; }
    float s = 0.f;
    #pragma unroll
    for (int d = 0; d < HD; d++) s = fmaf(qv[d], r[d], s);
    out[((size_t)bh * NTOK + q) * 32 + kidx] = s;
}

// ---------------- FA2-style fp16 flash attention (R11 proven) --------------
struct FlashSmem2 {
    __half Q[128][72];
    __half K[2][64][72];
    __half V[2][64][72];
    float  rh[128][36];
};

__global__ void __launch_bounds__(256) flash_attn_k(
    const float* __restrict__ qkv, const float* __restrict__ relh,
    const float* __restrict__ relw, float* __restrict__ outbuf)
{
    extern __shared__ char smraw[];
    FlashSmem2& sm = *reinterpret_cast<FlashSmem2*>(smraw);
    const int qt = blockIdx.x;
    const int bh = blockIdx.y;
    const int b = bh / HEADS, head = bh % HEADS;
    const float* Qg = qkv + (size_t)b * NTOK * QKVC + head * HD;
    const float* Kg = Qg + EMBED;
    const float* Vg = Qg + 2 * EMBED;
    const int tid = threadIdx.x, lane = tid & 31, wq = tid >> 5;
    const int g = lane >> 2, tg = lane & 3;

    const int sKey = tid >> 4;
    const int sD4  = (tid & 15) * 4;
    #pragma unroll
    for (int r = 0; r < 8; r++) {
        const int row = sKey + 16 * r;
        float4 v = *reinterpret_cast<const float4*>(
            Qg + (size_t)(qt * 128 + row) * QKVC + sD4);
        *reinterpret_cast<__half2*>(&sm.Q[row][sD4]) =
            __floats2half2_rn(v.x * 0.125f, v.y * 0.125f);
        *reinterpret_cast<__half2*>(&sm.Q[row][sD4 + 2]) =
            __floats2half2_rn(v.z * 0.125f, v.w * 0.125f);
    }
    for (int i = tid; i < 128 * 8; i += 256) {
        const int row = i >> 3, c4 = (i & 7) * 4;
        float4 v = *reinterpret_cast<const float4*>(
            relh + ((size_t)bh * NTOK + qt * 128 + row) * 32 + c4);
        *reinterpret_cast<float4*>(&sm.rh[row][c4]) = v;
    }
    const int q0 = qt * 128 + wq * 16 + g;
    float2 rwreg[2][4];
    #pragma unroll
    for (int r = 0; r < 2; r++) {
        const float* rwrow = relw + ((size_t)bh * NTOK + q0 + r * 8) * 32;
        #pragma unroll
        for (int j4 = 0; j4 < 4; j4++)
            rwreg[r][j4] = *reinterpret_cast<const float2*>(
                rwrow + j4 * 8 + tg * 2);
    }

    float m_r[2] = {-INFINITY, -INFINITY};
    float l_r[2] = {0.f, 0.f};
    float oacc[8][4];
    #pragma unroll
    for (int i = 0; i < 8; i++)
        #pragma unroll
        for (int j = 0; j < 4; j++) oacc[i][j] = 0.f;

    float4 pk[4], pv[4];
    #pragma unroll
    for (int r = 0; r < 4; r++) {
        pk[r] = *reinterpret_cast<const float4*>(
            Kg + (size_t)(sKey + 16 * r) * QKVC + sD4);
        pv[r] = *reinterpret_cast<const float4*>(
            Vg + (size_t)(sKey + 16 * r) * QKVC + sD4);
    }

    for (int t = 0; t < 16; t++) {
        const int buf = t & 1;
        #pragma unroll
        for (int r = 0; r < 4; r++) {
            const int row = sKey + 16 * r;
            *reinterpret_cast<__half2*>(&sm.K[buf][row][sD4]) =
                __floats2half2_rn(pk[r].x, pk[r].y);
            *reinterpret_cast<__half2*>(&sm.K[buf][row][sD4 + 2]) =
                __floats2half2_rn(pk[r].z, pk[r].w);
            *reinterpret_cast<__half2*>(&sm.V[buf][row][sD4]) =
                __floats2half2_rn(pv[r].x, pv[r].y);
            *reinterpret_cast<__half2*>(&sm.V[buf][row][sD4 + 2]) =
                __floats2half2_rn(pv[r].z, pv[r].w);
        }
        __syncthreads();
        if (t + 1 < 16) {
            #pragma unroll
            for (int r = 0; r < 4; r++) {
                pk[r] = *reinterpret_cast<const float4*>(
                    Kg + (size_t)((t + 1) * 64 + sKey + 16 * r) * QKVC + sD4);
                pv[r] = *reinterpret_cast<const float4*>(
                    Vg + (size_t)((t + 1) * 64 + sKey + 16 * r) * QKVC + sD4);
            }
        }
        float sacc[8][4];
        #pragma unroll
        for (int i = 0; i < 8; i++)
            #pragma unroll
            for (int j = 0; j < 4; j++) sacc[i][j] = 0.f;
        #pragma unroll
        for (int kf = 0; kf < 8; kf++) {
            const uint32_t a0 = *reinterpret_cast<const uint32_t*>(
                &sm.Q[wq * 16 + g][kf * 8 + tg * 2]);
            const uint32_t a1 = *reinterpret_cast<const uint32_t*>(
                &sm.Q[wq * 16 + 8 + g][kf * 8 + tg * 2]);
            #pragma unroll
            for (int nf = 0; nf < 8; nf++) {
                const uint32_t b0 = *reinterpret_cast<const uint32_t*>(
                    &sm.K[buf][nf * 8 + g][kf * 8 + tg * 2]);
                mma_f16k8(sacc[nf], a0, a1, b0);
            }
        }
        const float2 rhv0 = *reinterpret_cast<const float2*>(
            &sm.rh[wq * 16 + g][2 * t]);
        const float2 rhv1 = *reinterpret_cast<const float2*>(
            &sm.rh[wq * 16 + 8 + g][2 * t]);
        uint32_t ap0[8], ap1[8];
        #pragma unroll
        for (int r = 0; r < 2; r++) {
            const float2 rhv = r ? rhv1 : rhv0;
            float vals[8][2];
            float tmax = -INFINITY;
            #pragma unroll
            for (int nf = 0; nf < 8; nf++) {
                const float bias = (nf < 4 ? rhv.x : rhv.y);
                const float2 rwv = rwreg[r][nf & 3];
                float s0 = sacc[nf][2 * r + 0] + bias + rwv.x;
                float s1 = sacc[nf][2 * r + 1] + bias + rwv.y;
                vals[nf][0] = s0; vals[nf][1] = s1;
                tmax = fmaxf(tmax, fmaxf(s0, s1));
            }
            tmax = fmaxf(tmax, __shfl_xor_sync(0xffffffffu, tmax, 1));
            tmax = fmaxf(tmax, __shfl_xor_sync(0xffffffffu, tmax, 2));
            const float nm = fmaxf(m_r[r], tmax);
            float lsum = 0.f;
            #pragma unroll
            for (int nf = 0; nf < 8; nf++) {
                float p0 = __expf(vals[nf][0] - nm);
                float p1 = __expf(vals[nf][1] - nm);
                lsum += p0 + p1;
                uint32_t packed = h2_u32(__floats2half2_rn(p0, p1));
                if (r == 0) ap0[nf] = packed; else ap1[nf] = packed;
            }
            lsum += __shfl_xor_sync(0xffffffffu, lsum, 1);
            lsum += __shfl_xor_sync(0xffffffffu, lsum, 2);
            const float alpha = __expf(m_r[r] - nm);
            m_r[r] = nm;
            l_r[r] = l_r[r] * alpha + lsum;
            #pragma unroll
            for (int nfd = 0; nfd < 8; nfd++) {
                oacc[nfd][2 * r + 0] *= alpha;
                oacc[nfd][2 * r + 1] *= alpha;
            }
        }
        const uint32_t vbase = smem_u32(&sm.V[buf][0][0]);
        #pragma unroll
        for (int kf = 0; kf < 8; kf++) {
            #pragma unroll
            for (int nq = 0; nq < 2; nq++) {
                const int mat = lane >> 3;
                const int nfd = nq * 4 + mat;
                const uint32_t addr = vbase +
                    (uint32_t)((kf * 8 + (lane & 7)) * 144 + nfd * 16);
                uint32_t bf[4];
                ldsm_x4_trans(bf, addr);
                #pragma unroll
                for (int m2 = 0; m2 < 4; m2++)
                    mma_f16k8(oacc[nq * 4 + m2], ap0[kf], ap1[kf], bf[m2]);
            }
        }
    }
    const float li0 = 1.f / l_r[0];
    const float li1 = 1.f / l_r[1];
    #pragma unroll
    for (int nfd = 0; nfd < 8; nfd++) {
        const int d = nfd * 8 + tg * 2;
        float* dst0 = outbuf + ((size_t)b * NTOK + q0) * EMBED + head * HD + d;
        float* dst1 = dst0 + 8 * EMBED;
        *reinterpret_cast<float2*>(dst0) =
            make_float2(oacc[nfd][0] * li0, oacc[nfd][1] * li0);
        *reinterpret_cast<float2*>(dst1) =
            make_float2(oacc[nfd][2] * li1, oacc[nfd][3] * li1);
    }
}

// ---------------- host launcher ----------------
extern "C" void kernel_launch(void* const* d_in, const int* in_sizes, int n_in,
                              void* d_out, int out_size)
{
    const float* x       = (const float*)d_in[0];
    const float* conv_w  = (const float*)d_in[1];
    const float* conv_b  = (const float*)d_in[2];
    const float* pos     = (const float*)d_in[3];
    const float* ln1_w   = (const float*)d_in[4];
    const float* ln1_b   = (const float*)d_in[5];
    const float* qkv_w   = (const float*)d_in[6];
    const float* qkv_b   = (const float*)d_in[7];
    const float* proj_w  = (const float*)d_in[8];
    const float* proj_b  = (const float*)d_in[9];
    const float* rph     = (const float*)d_in[10];
    const float* rpw     = (const float*)d_in[11];
    const float* ln2_w   = (const float*)d_in[12];
    const float* ln2_b   = (const float*)d_in[13];
    const float* fc1_w   = (const float*)d_in[14];
    const float* fc1_b   = (const float*)d_in[15];
    const float* fc2_w   = (const float*)d_in[16];
    const float* fc2_b   = (const float*)d_in[17];
    float* out = (float*)d_out;

    float *h, *ln, *qkv, *attnout, *mlp, *relh, *relw, *col, *wt;
    cudaGetSymbolAddress((void**)&h, g_h);
    cudaGetSymbolAddress((void**)&ln, g_ln);
    cudaGetSymbolAddress((void**)&qkv, g_qkv);
    cudaGetSymbolAddress((void**)&attnout, g_attnout);
    cudaGetSymbolAddress((void**)&mlp, g_mlp);
    cudaGetSymbolAddress((void**)&relh, g_relh);
    cudaGetSymbolAddress((void**)&relw, g_relw);
    cudaGetSymbolAddress((void**)&col, g_col);
    cudaGetSymbolAddress((void**)&wt, g_wt);

    cudaFuncSetAttribute(flash_attn_k,
                         cudaFuncAttributeMaxDynamicSharedMemorySize,
                         (int)sizeof(FlashSmem2));

    transpose768_k<<<(EMBED * EMBED) / 256, 256>>>(conv_w, wt);
    im2col_k<<<(MTOT * EMBED) / 256, 256>>>(x, col);
    mma_gemm<4><<<dim3(EMBED / 128, MTOT / 128), 256>>>(
        MTOT, EMBED, EMBED, col, wt, h, conv_b, pos);

    for (int L = 0; L < DEPTH; L++) {
        layernorm_k<<<MTOT, 256>>>(h, ln1_w + L * EMBED, ln1_b + L * EMBED, ln);
        mma_gemm<1><<<dim3(QKVC / 128, MTOT / 128), 256>>>(
            MTOT, QKVC, EMBED, ln, qkv_w + (size_t)L * EMBED * QKVC, qkv,
            qkv_b + L * QKVC, nullptr);
        rel_tables_k<<<BH * NTOK, 64>>>(qkv, rph + L * RELT * HD,
                                        rpw + L * RELT * HD, relh, relw);
        flash_attn_k<<<dim3(8, BH), 256, sizeof(FlashSmem2)>>>(
            qkv, relh, relw, attnout);
        mma_gemm<2><<<dim3(EMBED / 128, MTOT / 128), 256>>>(
            MTOT, EMBED, EMBED, attnout, proj_w + (size_t)L * EMBED * EMBED, h,
            proj_b + L * EMBED, h);
        layernorm_k<<<MTOT, 256>>>(h, ln2_w + L * EMBED, ln2_b + L * EMBED, ln);
        mma_gemm<3><<<dim3(MLPD / 128, MTOT / 128), 256>>>(
            MTOT, MLPD, EMBED, ln, fc1_w + (size_t)L * EMBED * MLPD, mlp,
            fc1_b + L * MLPD, nullptr);
        float* dst = (L == DEPTH - 1) ? out : h;
        mma_gemm<2><<<dim3(EMBED / 128, MTOT / 128), 256>>>(
            MTOT, EMBED, MLPD, mlp, fc2_w + (size_t)L * MLPD * EMBED, dst,
            fc2_b + L * EMBED, h);
    }
}

// round 14
// speedup vs baseline: 1.2644x; 1.2644x over previous
#include <cuda_runtime.h>
#include <cuda_fp16.h>
#include <math.h>
#include <stdint.h>

// ---------------- problem constants ----------------
#define BATCH   4
#define NTOK    1024
#define EMBED   768
#define HEADS   12
#define HD      64
#define DEPTH   4
#define QKVC    2304
#define MLPD    3072
#define MTOT    4096
#define BH      48
#define RELT    63

// ---------------- scratch ----------------
__device__ float g_h[MTOT * EMBED];
__device__ float g_ln[MTOT * EMBED];
__device__ float g_qkv[MTOT * QKVC];
__device__ float g_attnout[MTOT * EMBED];
__device__ float g_mlp[MTOT * MLPD];
__device__ float g_relh[BH * NTOK * 32];
__device__ float g_relw[BH * NTOK * 32];
__device__ float g_col[MTOT * EMBED];
__device__ float g_wt[EMBED * EMBED];

// ---------------- helpers ----------------
__device__ __forceinline__ float gelu_exact(float x) {
    return 0.5f * x * (1.0f + erff(x * 0.70710678118654752440f));
}
__device__ __forceinline__ float blockSum256(float v, float* red) {
    const int tid = threadIdx.x;
    #pragma unroll
    for (int o = 16; o > 0; o >>= 1) v += __shfl_xor_sync(0xffffffffu, v, o);
    if ((tid & 31) == 0) red[tid >> 5] = v;
    __syncthreads();
    float t = 0.f;
    #pragma unroll
    for (int i = 0; i < 8; i++) t += red[i];
    return t;
}
__device__ __forceinline__ float rna_tf32(float x) {
    return __uint_as_float(__float_as_uint(x) + 0x1000u);
}
__device__ __forceinline__ float4 rna4(float4 v) {
    v.x = rna_tf32(v.x); v.y = rna_tf32(v.y);
    v.z = rna_tf32(v.z); v.w = rna_tf32(v.w);
    return v;
}
__device__ __forceinline__ uint32_t h2_u32(__half2 h) {
    uint32_t u;
    *reinterpret_cast<__half2*>(&u) = h;
    return u;
}
__device__ __forceinline__ void mma_tf32(float* d, const uint32_t* a,
                                         const uint32_t* b) {
    asm volatile(
        "mma.sync.aligned.m16n8k8.row.col.f32.tf32.tf32.f32 "
        "{%0,%1,%2,%3}, {%4,%5,%6,%7}, {%8,%9}, {%0,%1,%2,%3};\n"
        : "+f"(d[0]), "+f"(d[1]), "+f"(d[2]), "+f"(d[3])
        : "r"(a[0]), "r"(a[1]), "r"(a[2]), "r"(a[3]), "r"(b[0]), "r"(b[1]));
}
__device__ __forceinline__ void mma_f16k8(float* d, uint32_t a0, uint32_t a1,
                                          uint32_t b0) {
    asm volatile(
        "mma.sync.aligned.m16n8k8.row.col.f32.f16.f16.f32 "
        "{%0,%1,%2,%3}, {%4,%5}, {%6}, {%0,%1,%2,%3};\n"
        : "+f"(d[0]), "+f"(d[1]), "+f"(d[2]), "+f"(d[3])
        : "r"(a0), "r"(a1), "r"(b0));
}
__device__ __forceinline__ void ldsm_x4_trans(uint32_t* r, uint32_t addr) {
    asm volatile(
        "ldmatrix.sync.aligned.m8n8.x4.trans.shared.b16 {%0,%1,%2,%3}, [%4];"
        : "=r"(r[0]), "=r"(r[1]), "=r"(r[2]), "=r"(r[3]) : "r"(addr));
}
__device__ __forceinline__ uint32_t smem_u32(const void* p) {
    uint32_t a;
    asm("{ .reg .u64 t; cvta.to.shared.u64 t, %1; cvt.u32.u64 %0, t; }"
        : "=r"(a) : "l"(p));
    return a;
}

// ---------------- tf32 tensor-core GEMM (R11 proven) ----------
template <int EPI>
__global__ void __launch_bounds__(256) mma_gemm(
    int M, int N, int K,
    const float* __restrict__ A, const float* __restrict__ B,
    float* __restrict__ C,
    const float* __restrict__ bias, const float* __restrict__ res)
{
    constexpr int BM = 128, BN = 128, BK = 16;
    __shared__ float As[2][BM][BK + 4];
    __shared__ float Bs[2][BK][BN + 8];

    const int tid = threadIdx.x;
    const int lane = tid & 31;
    const int wid = tid >> 5;
    const int wm = wid & 1;
    const int wn = wid >> 1;
    const int g = lane >> 2, tg = lane & 3;

    const float* Ab = A + (size_t)blockIdx.y * BM * K;
    const float* Bb = B + blockIdx.x * BN;

    float acc[4][4][4];
    #pragma unroll
    for (int i = 0; i < 4; i++)
        #pragma unroll
        for (int j = 0; j < 4; j++)
            #pragma unroll
            for (int r = 0; r < 4; r++) acc[i][j][r] = 0.f;

    const int aRow0 = tid >> 2;
    const int aC4   = tid & 3;
    const int bRow0 = tid >> 5;
    const int bC4   = tid & 31;

    float4 ra[2], rb[2];
    const int nIter = K / BK;

    #pragma unroll
    for (int p = 0; p < 2; p++) {
        ra[p] = *reinterpret_cast<const float4*>(
            Ab + (size_t)(aRow0 + p * 64) * K + aC4 * 4);
        rb[p] = *reinterpret_cast<const float4*>(
            Bb + (size_t)(bRow0 + p * 8) * N + bC4 * 4);
    }
    #pragma unroll
    for (int p = 0; p < 2; p++) {
        *reinterpret_cast<float4*>(&As[0][aRow0 + p * 64][aC4 * 4]) = rna4(ra[p]);
        *reinterpret_cast<float4*>(&Bs[0][bRow0 + p * 8][bC4 * 4]) = rna4(rb[p]);
    }
    __syncthreads();

    int buf = 0;
    for (int it = 0; it < nIter; ++it) {
        if (it + 1 < nIter) {
            const int k0 = (it + 1) * BK;
            #pragma unroll
            for (int p = 0; p < 2; p++) {
                ra[p] = *reinterpret_cast<const float4*>(
                    Ab + (size_t)(aRow0 + p * 64) * K + k0 + aC4 * 4);
                rb[p] = *reinterpret_cast<const float4*>(
                    Bb + (size_t)(k0 + bRow0 + p * 8) * N + bC4 * 4);
            }
        }
        #pragma unroll
        for (int kf = 0; kf < 2; kf++) {
            uint32_t af[4][4];
            uint32_t bf[4][2];
            #pragma unroll
            for (int mf = 0; mf < 4; mf++) {
                const int r = wm * 64 + mf * 16;
                af[mf][0] = __float_as_uint(As[buf][r + g][kf * 8 + tg]);
                af[mf][1] = __float_as_uint(As[buf][r + 8 + g][kf * 8 + tg]);
                af[mf][2] = __float_as_uint(As[buf][r + g][kf * 8 + tg + 4]);
                af[mf][3] = __float_as_uint(As[buf][r + 8 + g][kf * 8 + tg + 4]);
            }
            #pragma unroll
            for (int nf = 0; nf < 4; nf++) {
                const int c = wn * 32 + nf * 8;
                bf[nf][0] = __float_as_uint(Bs[buf][kf * 8 + tg][c + g]);
                bf[nf][1] = __float_as_uint(Bs[buf][kf * 8 + tg + 4][c + g]);
            }
            #pragma unroll
            for (int mf = 0; mf < 4; mf++)
                #pragma unroll
                for (int nf = 0; nf < 4; nf++)
                    mma_tf32(acc[mf][nf], af[mf], bf[nf]);
        }
        if (it + 1 < nIter) {
            #pragma unroll
            for (int p = 0; p < 2; p++) {
                *reinterpret_cast<float4*>(&As[buf ^ 1][aRow0 + p * 64][aC4 * 4]) =
                    rna4(ra[p]);
                *reinterpret_cast<float4*>(&Bs[buf ^ 1][bRow0 + p * 8][bC4 * 4]) =
                    rna4(rb[p]);
            }
        }
        __syncthreads();
        buf ^= 1;
    }

    #pragma unroll
    for (int mf = 0; mf < 4; mf++) {
        const int row0 = blockIdx.y * 128 + wm * 64 + mf * 16 + g;
        #pragma unroll
        for (int nf = 0; nf < 4; nf++) {
            const int col = blockIdx.x * 128 + wn * 32 + nf * 8 + tg * 2;
            #pragma unroll
            for (int half = 0; half < 2; half++) {
                const int m = row0 + half * 8;
                float c0 = acc[mf][nf][half * 2 + 0];
                float c1 = acc[mf][nf][half * 2 + 1];
                if (EPI == 1) {
                    c0 += bias[col]; c1 += bias[col + 1];
                } else if (EPI == 2) {
                    float2 rv = *reinterpret_cast<const float2*>(
                        res + (size_t)m * N + col);
                    c0 += bias[col]     + rv.x;
                    c1 += bias[col + 1] + rv.y;
                } else if (EPI == 3) {
                    c0 = gelu_exact(c0 + bias[col]);
                    c1 = gelu_exact(c1 + bias[col + 1]);
                } else if (EPI == 4) {
                    float2 rv = *reinterpret_cast<const float2*>(
                        res + (size_t)(m & (NTOK - 1)) * N + col);
                    c0 += bias[col]     + rv.x;
                    c1 += bias[col + 1] + rv.y;
                }
                *reinterpret_cast<float2*>(&C[(size_t)m * N + col]) =
                    make_float2(c0, c1);
            }
        }
    }
}

// ---------------- im2col ----------------
__global__ void __launch_bounds__(256) im2col_k(const float* __restrict__ x,
                                                float* __restrict__ col)
{
    int idx = blockIdx.x * 256 + threadIdx.x;
    int m = idx / EMBED, k = idx - m * EMBED;
    int b = m >> 10;
    int gy = (m >> 5) & 31, gx = m & 31;
    int ci = k >> 8;
    int ph = (k >> 4) & 15, pw = k & 15;
    col[idx] = x[(((size_t)b * 3 + ci) * 512 + gy * 16 + ph) * 512 + gx * 16 + pw];
}

__global__ void __launch_bounds__(256) transpose768_k(const float* __restrict__ w,
                                                      float* __restrict__ wt)
{
    int idx = blockIdx.x * 256 + threadIdx.x;
    int k = idx / EMBED, co = idx - k * EMBED;
    wt[idx] = w[(size_t)co * EMBED + k];
}

// ---------------- LayerNorm ----------------
__global__ void __launch_bounds__(256) layernorm_k(
    const float* __restrict__ in, const float* __restrict__ w,
    const float* __restrict__ b, float* __restrict__ out)
{
    __shared__ float red[8];
    const int tid = threadIdx.x;
    const float* p = in + (size_t)blockIdx.x * EMBED;
    float* q = out + (size_t)blockIdx.x * EMBED;
    float x0 = p[tid], x1 = p[tid + 256], x2 = p[tid + 512];
    float s  = blockSum256(x0 + x1 + x2, red);
    __syncthreads();
    float sq = blockSum256(x0 * x0 + x1 * x1 + x2 * x2, red);
    float mean = s * (1.f / 768.f);
    float var = sq * (1.f / 768.f) - mean * mean;
    float rs = rsqrtf(var + 1e-5f);
    q[tid]       = (x0 - mean) * rs * w[tid]       + b[tid];
    q[tid + 256] = (x1 - mean) * rs * w[tid + 256] + b[tid + 256];
    q[tid + 512] = (x2 - mean) * rs * w[tid + 512] + b[tid + 512];
}

// ---------------- rel-pos bias tables (256-thread blocks, 4 groups) --------
__global__ void __launch_bounds__(256) rel_tables_k(
    const float* __restrict__ qkv, const float* __restrict__ rph,
    const float* __restrict__ rpw, float* __restrict__ relh,
    float* __restrict__ relw)
{
    __shared__ float qv[4][HD];
    const int tid = threadIdx.x;
    const int grp = tid >> 6;          // 0..3
    const int gt  = tid & 63;          // thread in group
    const int bq = blockIdx.x * 4 + grp;
    const int bh = bq >> 10, q = bq & 1023;
    const int b = bh / HEADS, head = bh % HEADS;
    const int hq = q >> 5, wq = q & 31;
    qv[grp][gt] = qkv[((size_t)(b * NTOK + q)) * QKVC + head * HD + gt];
    __syncthreads();
    const int kidx = gt & 31;
    const float* r;
    float* out;
    if (gt < 32) { r = rph + (hq - kidx + 31) * HD; out = relh; }
    else         { r = rpw + (wq - kidx + 31) * HD; out = relw; }
    float s = 0.f;
    #pragma unroll
    for (int d = 0; d < HD; d++) s = fmaf(qv[grp][d], r[d], s);
    out[((size_t)bh * NTOK + q) * 32 + kidx] = s;
}

// ---------------- FA2-style fp16 flash attention (R11 proven) --------------
struct FlashSmem2 {
    __half Q[128][72];
    __half K[2][64][72];
    __half V[2][64][72];
    float  rh[128][36];
};

__global__ void __launch_bounds__(256) flash_attn_k(
    const float* __restrict__ qkv, const float* __restrict__ relh,
    const float* __restrict__ relw, float* __restrict__ outbuf)
{
    extern __shared__ char smraw[];
    FlashSmem2& sm = *reinterpret_cast<FlashSmem2*>(smraw);
    const int qt = blockIdx.x;
    const int bh = blockIdx.y;
    const int b = bh / HEADS, head = bh % HEADS;
    const float* Qg = qkv + (size_t)b * NTOK * QKVC + head * HD;
    const float* Kg = Qg + EMBED;
    const float* Vg = Qg + 2 * EMBED;
    const int tid = threadIdx.x, lane = tid & 31, wq = tid >> 5;
    const int g = lane >> 2, tg = lane & 3;

    const int sKey = tid >> 4;
    const int sD4  = (tid & 15) * 4;
    #pragma unroll
    for (int r = 0; r < 8; r++) {
        const int row = sKey + 16 * r;
        float4 v = *reinterpret_cast<const float4*>(
            Qg + (size_t)(qt * 128 + row) * QKVC + sD4);
        *reinterpret_cast<__half2*>(&sm.Q[row][sD4]) =
            __floats2half2_rn(v.x * 0.125f, v.y * 0.125f);
        *reinterpret_cast<__half2*>(&sm.Q[row][sD4 + 2]) =
            __floats2half2_rn(v.z * 0.125f, v.w * 0.125f);
    }
    for (int i = tid; i < 128 * 8; i += 256) {
        const int row = i >> 3, c4 = (i & 7) * 4;
        float4 v = *reinterpret_cast<const float4*>(
            relh + ((size_t)bh * NTOK + qt * 128 + row) * 32 + c4);
        *reinterpret_cast<float4*>(&sm.rh[row][c4]) = v;
    }
    const int q0 = qt * 128 + wq * 16 + g;
    float2 rwreg[2][4];
    #pragma unroll
    for (int r = 0; r < 2; r++) {
        const float* rwrow = relw + ((size_t)bh * NTOK + q0 + r * 8) * 32;
        #pragma unroll
        for (int j4 = 0; j4 < 4; j4++)
            rwreg[r][j4] = *reinterpret_cast<const float2*>(
                rwrow + j4 * 8 + tg * 2);
    }

    float m_r[2] = {-INFINITY, -INFINITY};
    float l_r[2] = {0.f, 0.f};
    float oacc[8][4];
    #pragma unroll
    for (int i = 0; i < 8; i++)
        #pragma unroll
        for (int j = 0; j < 4; j++) oacc[i][j] = 0.f;

    float4 pk[4], pv[4];
    #pragma unroll
    for (int r = 0; r < 4; r++) {
        pk[r] = *reinterpret_cast<const float4*>(
            Kg + (size_t)(sKey + 16 * r) * QKVC + sD4);
        pv[r] = *reinterpret_cast<const float4*>(
            Vg + (size_t)(sKey + 16 * r) * QKVC + sD4);
    }

    for (int t = 0; t < 16; t++) {
        const int buf = t & 1;
        #pragma unroll
        for (int r = 0; r < 4; r++) {
            const int row = sKey + 16 * r;
            *reinterpret_cast<__half2*>(&sm.K[buf][row][sD4]) =
                __floats2half2_rn(pk[r].x, pk[r].y);
            *reinterpret_cast<__half2*>(&sm.K[buf][row][sD4 + 2]) =
                __floats2half2_rn(pk[r].z, pk[r].w);
            *reinterpret_cast<__half2*>(&sm.V[buf][row][sD4]) =
                __floats2half2_rn(pv[r].x, pv[r].y);
            *reinterpret_cast<__half2*>(&sm.V[buf][row][sD4 + 2]) =
                __floats2half2_rn(pv[r].z, pv[r].w);
        }
        __syncthreads();
        if (t + 1 < 16) {
            #pragma unroll
            for (int r = 0; r < 4; r++) {
                pk[r] = *reinterpret_cast<const float4*>(
                    Kg + (size_t)((t + 1) * 64 + sKey + 16 * r) * QKVC + sD4);
                pv[r] = *reinterpret_cast<const float4*>(
                    Vg + (size_t)((t + 1) * 64 + sKey + 16 * r) * QKVC + sD4);
            }
        }
        float sacc[8][4];
        #pragma unroll
        for (int i = 0; i < 8; i++)
            #pragma unroll
            for (int j = 0; j < 4; j++) sacc[i][j] = 0.f;
        #pragma unroll
        for (int kf = 0; kf < 8; kf++) {
            const uint32_t a0 = *reinterpret_cast<const uint32_t*>(
                &sm.Q[wq * 16 + g][kf * 8 + tg * 2]);
            const uint32_t a1 = *reinterpret_cast<const uint32_t*>(
                &sm.Q[wq * 16 + 8 + g][kf * 8 + tg * 2]);
            #pragma unroll
            for (int nf = 0; nf < 8; nf++) {
                const uint32_t b0 = *reinterpret_cast<const uint32_t*>(
                    &sm.K[buf][nf * 8 + g][kf * 8 + tg * 2]);
                mma_f16k8(sacc[nf], a0, a1, b0);
            }
        }
        const float2 rhv0 = *reinterpret_cast<const float2*>(
            &sm.rh[wq * 16 + g][2 * t]);
        const float2 rhv1 = *reinterpret_cast<const float2*>(
            &sm.rh[wq * 16 + 8 + g][2 * t]);
        uint32_t ap0[8], ap1[8];
        #pragma unroll
        for (int r = 0; r < 2; r++) {
            const float2 rhv = r ? rhv1 : rhv0;
            float vals[8][2];
            float tmax = -INFINITY;
            #pragma unroll
            for (int nf = 0; nf < 8; nf++) {
                const float bias = (nf < 4 ? rhv.x : rhv.y);
                const float2 rwv = rwreg[r][nf & 3];
                float s0 = sacc[nf][2 * r + 0] + bias + rwv.x;
                float s1 = sacc[nf][2 * r + 1] + bias + rwv.y;
                vals[nf][0] = s0; vals[nf][1] = s1;
                tmax = fmaxf(tmax, fmaxf(s0, s1));
            }
            tmax = fmaxf(tmax, __shfl_xor_sync(0xffffffffu, tmax, 1));
            tmax = fmaxf(tmax, __shfl_xor_sync(0xffffffffu, tmax, 2));
            const float nm = fmaxf(m_r[r], tmax);
            float lsum = 0.f;
            #pragma unroll
            for (int nf = 0; nf < 8; nf++) {
                float p0 = __expf(vals[nf][0] - nm);
                float p1 = __expf(vals[nf][1] - nm);
                lsum += p0 + p1;
                uint32_t packed = h2_u32(__floats2half2_rn(p0, p1));
                if (r == 0) ap0[nf] = packed; else ap1[nf] = packed;
            }
            lsum += __shfl_xor_sync(0xffffffffu, lsum, 1);
            lsum += __shfl_xor_sync(0xffffffffu, lsum, 2);
            const float alpha = __expf(m_r[r] - nm);
            m_r[r] = nm;
            l_r[r] = l_r[r] * alpha + lsum;
            #pragma unroll
            for (int nfd = 0; nfd < 8; nfd++) {
                oacc[nfd][2 * r + 0] *= alpha;
                oacc[nfd][2 * r + 1] *= alpha;
            }
        }
        const uint32_t vbase = smem_u32(&sm.V[buf][0][0]);
        #pragma unroll
        for (int kf = 0; kf < 8; kf++) {
            #pragma unroll
            for (int nq = 0; nq < 2; nq++) {
                const int mat = lane >> 3;
                const int nfd = nq * 4 + mat;
                const uint32_t addr = vbase +
                    (uint32_t)((kf * 8 + (lane & 7)) * 144 + nfd * 16);
                uint32_t bf[4];
                ldsm_x4_trans(bf, addr);
                #pragma unroll
                for (int m2 = 0; m2 < 4; m2++)
                    mma_f16k8(oacc[nq * 4 + m2], ap0[kf], ap1[kf], bf[m2]);
            }
        }
    }
    const float li0 = 1.f / l_r[0];
    const float li1 = 1.f / l_r[1];
    #pragma unroll
    for (int nfd = 0; nfd < 8; nfd++) {
        const int d = nfd * 8 + tg * 2;
        float* dst0 = outbuf + ((size_t)b * NTOK + q0) * EMBED + head * HD + d;
        float* dst1 = dst0 + 8 * EMBED;
        *reinterpret_cast<float2*>(dst0) =
            make_float2(oacc[nfd][0] * li0, oacc[nfd][1] * li0);
        *reinterpret_cast<float2*>(dst1) =
            make_float2(oacc[nfd][2] * li1, oacc[nfd][3] * li1);
    }
}

// ---------------- host launcher ----------------
extern "C" void kernel_launch(void* const* d_in, const int* in_sizes, int n_in,
                              void* d_out, int out_size)
{
    const float* x       = (const float*)d_in[0];
    const float* conv_w  = (const float*)d_in[1];
    const float* conv_b  = (const float*)d_in[2];
    const float* pos     = (const float*)d_in[3];
    const float* ln1_w   = (const float*)d_in[4];
    const float* ln1_b   = (const float*)d_in[5];
    const float* qkv_w   = (const float*)d_in[6];
    const float* qkv_b   = (const float*)d_in[7];
    const float* proj_w  = (const float*)d_in[8];
    const float* proj_b  = (const float*)d_in[9];
    const float* rph     = (const float*)d_in[10];
    const float* rpw     = (const float*)d_in[11];
    const float* ln2_w   = (const float*)d_in[12];
    const float* ln2_b   = (const float*)d_in[13];
    const float* fc1_w   = (const float*)d_in[14];
    const float* fc1_b   = (const float*)d_in[15];
    const float* fc2_w   = (const float*)d_in[16];
    const float* fc2_b   = (const float*)d_in[17];
    float* out = (float*)d_out;

    float *h, *ln, *qkv, *attnout, *mlp, *relh, *relw, *col, *wt;
    cudaGetSymbolAddress((void**)&h, g_h);
    cudaGetSymbolAddress((void**)&ln, g_ln);
    cudaGetSymbolAddress((void**)&qkv, g_qkv);
    cudaGetSymbolAddress((void**)&attnout, g_attnout);
    cudaGetSymbolAddress((void**)&mlp, g_mlp);
    cudaGetSymbolAddress((void**)&relh, g_relh);
    cudaGetSymbolAddress((void**)&relw, g_relw);
    cudaGetSymbolAddress((void**)&col, g_col);
    cudaGetSymbolAddress((void**)&wt, g_wt);

    cudaFuncSetAttribute(flash_attn_k,
                         cudaFuncAttributeMaxDynamicSharedMemorySize,
                         (int)sizeof(FlashSmem2));

    transpose768_k<<<(EMBED * EMBED) / 256, 256>>>(conv_w, wt);
    im2col_k<<<(MTOT * EMBED) / 256, 256>>>(x, col);
    mma_gemm<4><<<dim3(EMBED / 128, MTOT / 128), 256>>>(
        MTOT, EMBED, EMBED, col, wt, h, conv_b, pos);

    for (int L = 0; L < DEPTH; L++) {
        layernorm_k<<<MTOT, 256>>>(h, ln1_w + L * EMBED, ln1_b + L * EMBED, ln);
        mma_gemm<1><<<dim3(QKVC / 128, MTOT / 128), 256>>>(
            MTOT, QKVC, EMBED, ln, qkv_w + (size_t)L * EMBED * QKVC, qkv,
            qkv_b + L * QKVC, nullptr);
        rel_tables_k<<<BH * NTOK / 4, 256>>>(qkv, rph + L * RELT * HD,
                                             rpw + L * RELT * HD, relh, relw);
        flash_attn_k<<<dim3(8, BH), 256, sizeof(FlashSmem2)>>>(
            qkv, relh, relw, attnout);
        mma_gemm<2><<<dim3(EMBED / 128, MTOT / 128), 256>>>(
            MTOT, EMBED, EMBED, attnout, proj_w + (size_t)L * EMBED * EMBED, h,
            proj_b + L * EMBED, h);
        layernorm_k<<<MTOT, 256>>>(h, ln2_w + L * EMBED, ln2_b + L * EMBED, ln);
        mma_gemm<3><<<dim3(MLPD / 128, MTOT / 128), 256>>>(
            MTOT, MLPD, EMBED, ln, fc1_w + (size_t)L * EMBED * MLPD, mlp,
            fc1_b + L * MLPD, nullptr);
        float* dst = (L == DEPTH - 1) ? out : h;
        mma_gemm<2><<<dim3(EMBED / 128, MTOT / 128), 256>>>(
            MTOT, EMBED, MLPD, mlp, fc2_w + (size_t)L * MLPD * EMBED, dst,
            fc2_b + L * EMBED, h);
    }
}

// round 15
// speedup vs baseline: 1.2848x; 1.0161x over previous
#include <cuda_runtime.h>
#include <cuda_fp16.h>
#include <math.h>
#include <stdint.h>

// ---------------- problem constants ----------------
#define BATCH   4
#define NTOK    1024
#define EMBED   768
#define HEADS   12
#define HD      64
#define DEPTH   4
#define QKVC    2304
#define MLPD    3072
#define MTOT    4096
#define BH      48
#define RELT    63

// ---------------- scratch ----------------
__device__ float g_h[MTOT * EMBED];
__device__ float g_ln[MTOT * EMBED];
__device__ float g_qkv[MTOT * QKVC];
__device__ float g_attnout[MTOT * EMBED];
__device__ float g_mlp[MTOT * MLPD];
__device__ float g_relh[BH * NTOK * 32];
__device__ float g_relw[BH * NTOK * 32];
__device__ float g_col[MTOT * EMBED];
__device__ float g_wt[EMBED * EMBED];

// ---------------- helpers ----------------
__device__ __forceinline__ float gelu_exact(float x) {
    return 0.5f * x * (1.0f + erff(x * 0.70710678118654752440f));
}
__device__ __forceinline__ float blockSum256(float v, float* red) {
    const int tid = threadIdx.x;
    #pragma unroll
    for (int o = 16; o > 0; o >>= 1) v += __shfl_xor_sync(0xffffffffu, v, o);
    if ((tid & 31) == 0) red[tid >> 5] = v;
    __syncthreads();
    float t = 0.f;
    #pragma unroll
    for (int i = 0; i < 8; i++) t += red[i];
    return t;
}
__device__ __forceinline__ float rna_tf32(float x) {
    return __uint_as_float(__float_as_uint(x) + 0x1000u);
}
__device__ __forceinline__ float4 rna4(float4 v) {
    v.x = rna_tf32(v.x); v.y = rna_tf32(v.y);
    v.z = rna_tf32(v.z); v.w = rna_tf32(v.w);
    return v;
}
__device__ __forceinline__ uint32_t h2_u32(__half2 h) {
    uint32_t u;
    *reinterpret_cast<__half2*>(&u) = h;
    return u;
}
__device__ __forceinline__ void mma_tf32(float* d, const uint32_t* a,
                                         const uint32_t* b) {
    asm volatile(
        "mma.sync.aligned.m16n8k8.row.col.f32.tf32.tf32.f32 "
        "{%0,%1,%2,%3}, {%4,%5,%6,%7}, {%8,%9}, {%0,%1,%2,%3};\n"
        : "+f"(d[0]), "+f"(d[1]), "+f"(d[2]), "+f"(d[3])
        : "r"(a[0]), "r"(a[1]), "r"(a[2]), "r"(a[3]), "r"(b[0]), "r"(b[1]));
}
__device__ __forceinline__ void mma_f16k8(float* d, uint32_t a0, uint32_t a1,
                                          uint32_t b0) {
    asm volatile(
        "mma.sync.aligned.m16n8k8.row.col.f32.f16.f16.f32 "
        "{%0,%1,%2,%3}, {%4,%5}, {%6}, {%0,%1,%2,%3};\n"
        : "+f"(d[0]), "+f"(d[1]), "+f"(d[2]), "+f"(d[3])
        : "r"(a0), "r"(a1), "r"(b0));
}
__device__ __forceinline__ void ldsm_x4_trans(uint32_t* r, uint32_t addr) {
    asm volatile(
        "ldmatrix.sync.aligned.m8n8.x4.trans.shared.b16 {%0,%1,%2,%3}, [%4];"
        : "=r"(r[0]), "=r"(r[1]), "=r"(r[2]), "=r"(r[3]) : "r"(addr));
}
__device__ __forceinline__ uint32_t smem_u32(const void* p) {
    uint32_t a;
    asm("{ .reg .u64 t; cvta.to.shared.u64 t, %1; cvt.u32.u64 %0, t; }"
        : "=r"(a) : "l"(p));
    return a;
}

// ---------------- tf32 tensor-core GEMM, templated BM (R11 core) -----------
// BM in {128, 64}. 8 warps as 2x4; each warp: (BM/32) m-frags x 4 n-frags.
template <int EPI, int BM>
__global__ void __launch_bounds__(256) mma_gemm(
    int M, int N, int K,
    const float* __restrict__ A, const float* __restrict__ B,
    float* __restrict__ C,
    const float* __restrict__ bias, const float* __restrict__ res)
{
    constexpr int BN = 128, BK = 16;
    constexpr int MFRAG = BM / 32;       // 4 or 2
    constexpr int APASS = BM / 64;       // 2 or 1
    __shared__ float As[2][BM][BK + 4];
    __shared__ float Bs[2][BK][BN + 8];

    const int tid = threadIdx.x;
    const int lane = tid & 31;
    const int wid = tid >> 5;
    const int wm = wid & 1;
    const int wn = wid >> 1;
    const int g = lane >> 2, tg = lane & 3;

    const float* Ab = A + (size_t)blockIdx.y * BM * K;
    const float* Bb = B + blockIdx.x * BN;

    float acc[MFRAG][4][4];
    #pragma unroll
    for (int i = 0; i < MFRAG; i++)
        #pragma unroll
        for (int j = 0; j < 4; j++)
            #pragma unroll
            for (int r = 0; r < 4; r++) acc[i][j][r] = 0.f;

    const int aRow0 = tid >> 2;          // 0..63 (+p*64)
    const int aC4   = tid & 3;
    const int bRow0 = tid >> 5;
    const int bC4   = tid & 31;

    float4 ra[APASS], rb[2];
    const int nIter = K / BK;

    #pragma unroll
    for (int p = 0; p < APASS; p++)
        ra[p] = *reinterpret_cast<const float4*>(
            Ab + (size_t)(aRow0 + p * 64) * K + aC4 * 4);
    #pragma unroll
    for (int p = 0; p < 2; p++)
        rb[p] = *reinterpret_cast<const float4*>(
            Bb + (size_t)(bRow0 + p * 8) * N + bC4 * 4);
    #pragma unroll
    for (int p = 0; p < APASS; p++)
        *reinterpret_cast<float4*>(&As[0][aRow0 + p * 64][aC4 * 4]) = rna4(ra[p]);
    #pragma unroll
    for (int p = 0; p < 2; p++)
        *reinterpret_cast<float4*>(&Bs[0][bRow0 + p * 8][bC4 * 4]) = rna4(rb[p]);
    __syncthreads();

    int buf = 0;
    for (int it = 0; it < nIter; ++it) {
        if (it + 1 < nIter) {
            const int k0 = (it + 1) * BK;
            #pragma unroll
            for (int p = 0; p < APASS; p++)
                ra[p] = *reinterpret_cast<const float4*>(
                    Ab + (size_t)(aRow0 + p * 64) * K + k0 + aC4 * 4);
            #pragma unroll
            for (int p = 0; p < 2; p++)
                rb[p] = *reinterpret_cast<const float4*>(
                    Bb + (size_t)(k0 + bRow0 + p * 8) * N + bC4 * 4);
        }
        #pragma unroll
        for (int kf = 0; kf < 2; kf++) {
            uint32_t af[MFRAG][4];
            uint32_t bf[4][2];
            #pragma unroll
            for (int mf = 0; mf < MFRAG; mf++) {
                const int r = wm * (BM / 2) + mf * 16;
                af[mf][0] = __float_as_uint(As[buf][r + g][kf * 8 + tg]);
                af[mf][1] = __float_as_uint(As[buf][r + 8 + g][kf * 8 + tg]);
                af[mf][2] = __float_as_uint(As[buf][r + g][kf * 8 + tg + 4]);
                af[mf][3] = __float_as_uint(As[buf][r + 8 + g][kf * 8 + tg + 4]);
            }
            #pragma unroll
            for (int nf = 0; nf < 4; nf++) {
                const int c = wn * 32 + nf * 8;
                bf[nf][0] = __float_as_uint(Bs[buf][kf * 8 + tg][c + g]);
                bf[nf][1] = __float_as_uint(Bs[buf][kf * 8 + tg + 4][c + g]);
            }
            #pragma unroll
            for (int mf = 0; mf < MFRAG; mf++)
                #pragma unroll
                for (int nf = 0; nf < 4; nf++)
                    mma_tf32(acc[mf][nf], af[mf], bf[nf]);
        }
        if (it + 1 < nIter) {
            #pragma unroll
            for (int p = 0; p < APASS; p++)
                *reinterpret_cast<float4*>(&As[buf ^ 1][aRow0 + p * 64][aC4 * 4]) =
                    rna4(ra[p]);
            #pragma unroll
            for (int p = 0; p < 2; p++)
                *reinterpret_cast<float4*>(&Bs[buf ^ 1][bRow0 + p * 8][bC4 * 4]) =
                    rna4(rb[p]);
        }
        __syncthreads();
        buf ^= 1;
    }

    #pragma unroll
    for (int mf = 0; mf < MFRAG; mf++) {
        const int row0 = blockIdx.y * BM + wm * (BM / 2) + mf * 16 + g;
        #pragma unroll
        for (int nf = 0; nf < 4; nf++) {
            const int col = blockIdx.x * BN + wn * 32 + nf * 8 + tg * 2;
            #pragma unroll
            for (int half = 0; half < 2; half++) {
                const int m = row0 + half * 8;
                float c0 = acc[mf][nf][half * 2 + 0];
                float c1 = acc[mf][nf][half * 2 + 1];
                if (EPI == 1) {
                    c0 += bias[col]; c1 += bias[col + 1];
                } else if (EPI == 2) {
                    float2 rv = *reinterpret_cast<const float2*>(
                        res + (size_t)m * N + col);
                    c0 += bias[col]     + rv.x;
                    c1 += bias[col + 1] + rv.y;
                } else if (EPI == 3) {
                    c0 = gelu_exact(c0 + bias[col]);
                    c1 = gelu_exact(c1 + bias[col + 1]);
                } else if (EPI == 4) {
                    float2 rv = *reinterpret_cast<const float2*>(
                        res + (size_t)(m & (NTOK - 1)) * N + col);
                    c0 += bias[col]     + rv.x;
                    c1 += bias[col + 1] + rv.y;
                }
                *reinterpret_cast<float2*>(&C[(size_t)m * N + col]) =
                    make_float2(c0, c1);
            }
        }
    }
}

// ---------------- im2col ----------------
__global__ void __launch_bounds__(256) im2col_k(const float* __restrict__ x,
                                                float* __restrict__ col)
{
    int idx = blockIdx.x * 256 + threadIdx.x;
    int m = idx / EMBED, k = idx - m * EMBED;
    int b = m >> 10;
    int gy = (m >> 5) & 31, gx = m & 31;
    int ci = k >> 8;
    int ph = (k >> 4) & 15, pw = k & 15;
    col[idx] = x[(((size_t)b * 3 + ci) * 512 + gy * 16 + ph) * 512 + gx * 16 + pw];
}

__global__ void __launch_bounds__(256) transpose768_k(const float* __restrict__ w,
                                                      float* __restrict__ wt)
{
    int idx = blockIdx.x * 256 + threadIdx.x;
    int k = idx / EMBED, co = idx - k * EMBED;
    wt[idx] = w[(size_t)co * EMBED + k];
}

// ---------------- LayerNorm ----------------
__global__ void __launch_bounds__(256) layernorm_k(
    const float* __restrict__ in, const float* __restrict__ w,
    const float* __restrict__ b, float* __restrict__ out)
{
    __shared__ float red[8];
    const int tid = threadIdx.x;
    const float* p = in + (size_t)blockIdx.x * EMBED;
    float* q = out + (size_t)blockIdx.x * EMBED;
    float x0 = p[tid], x1 = p[tid + 256], x2 = p[tid + 512];
    float s  = blockSum256(x0 + x1 + x2, red);
    __syncthreads();
    float sq = blockSum256(x0 * x0 + x1 * x1 + x2 * x2, red);
    float mean = s * (1.f / 768.f);
    float var = sq * (1.f / 768.f) - mean * mean;
    float rs = rsqrtf(var + 1e-5f);
    q[tid]       = (x0 - mean) * rs * w[tid]       + b[tid];
    q[tid + 256] = (x1 - mean) * rs * w[tid + 256] + b[tid + 256];
    q[tid + 512] = (x2 - mean) * rs * w[tid + 512] + b[tid + 512];
}

// ---------------- rel-pos bias tables (256-thread blocks, 4 groups) --------
__global__ void __launch_bounds__(256) rel_tables_k(
    const float* __restrict__ qkv, const float* __restrict__ rph,
    const float* __restrict__ rpw, float* __restrict__ relh,
    float* __restrict__ relw)
{
    __shared__ float qv[4][HD];
    const int tid = threadIdx.x;
    const int grp = tid >> 6;
    const int gt  = tid & 63;
    const int bq = blockIdx.x * 4 + grp;
    const int bh = bq >> 10, q = bq & 1023;
    const int b = bh / HEADS, head = bh % HEADS;
    const int hq = q >> 5, wq = q & 31;
    qv[grp][gt] = qkv[((size_t)(b * NTOK + q)) * QKVC + head * HD + gt];
    __syncthreads();
    const int kidx = gt & 31;
    const float* r;
    float* out;
    if (gt < 32) { r = rph + (hq - kidx + 31) * HD; out = relh; }
    else         { r = rpw + (wq - kidx + 31) * HD; out = relw; }
    float s = 0.f;
    #pragma unroll
    for (int d = 0; d < HD; d++) s = fmaf(qv[grp][d], r[d], s);
    out[((size_t)bh * NTOK + q) * 32 + kidx] = s;
}

// ---------------- FA2-style fp16 flash attention (R11 proven) --------------
struct FlashSmem2 {
    __half Q[128][72];
    __half K[2][64][72];
    __half V[2][64][72];
    float  rh[128][36];
};

__global__ void __launch_bounds__(256) flash_attn_k(
    const float* __restrict__ qkv, const float* __restrict__ relh,
    const float* __restrict__ relw, float* __restrict__ outbuf)
{
    extern __shared__ char smraw[];
    FlashSmem2& sm = *reinterpret_cast<FlashSmem2*>(smraw);
    const int qt = blockIdx.x;
    const int bh = blockIdx.y;
    const int b = bh / HEADS, head = bh % HEADS;
    const float* Qg = qkv + (size_t)b * NTOK * QKVC + head * HD;
    const float* Kg = Qg + EMBED;
    const float* Vg = Qg + 2 * EMBED;
    const int tid = threadIdx.x, lane = tid & 31, wq = tid >> 5;
    const int g = lane >> 2, tg = lane & 3;

    const int sKey = tid >> 4;
    const int sD4  = (tid & 15) * 4;
    #pragma unroll
    for (int r = 0; r < 8; r++) {
        const int row = sKey + 16 * r;
        float4 v = *reinterpret_cast<const float4*>(
            Qg + (size_t)(qt * 128 + row) * QKVC + sD4);
        *reinterpret_cast<__half2*>(&sm.Q[row][sD4]) =
            __floats2half2_rn(v.x * 0.125f, v.y * 0.125f);
        *reinterpret_cast<__half2*>(&sm.Q[row][sD4 + 2]) =
            __floats2half2_rn(v.z * 0.125f, v.w * 0.125f);
    }
    for (int i = tid; i < 128 * 8; i += 256) {
        const int row = i >> 3, c4 = (i & 7) * 4;
        float4 v = *reinterpret_cast<const float4*>(
            relh + ((size_t)bh * NTOK + qt * 128 + row) * 32 + c4);
        *reinterpret_cast<float4*>(&sm.rh[row][c4]) = v;
    }
    const int q0 = qt * 128 + wq * 16 + g;
    float2 rwreg[2][4];
    #pragma unroll
    for (int r = 0; r < 2; r++) {
        const float* rwrow = relw + ((size_t)bh * NTOK + q0 + r * 8) * 32;
        #pragma unroll
        for (int j4 = 0; j4 < 4; j4++)
            rwreg[r][j4] = *reinterpret_cast<const float2*>(
                rwrow + j4 * 8 + tg * 2);
    }

    float m_r[2] = {-INFINITY, -INFINITY};
    float l_r[2] = {0.f, 0.f};
    float oacc[8][4];
    #pragma unroll
    for (int i = 0; i < 8; i++)
        #pragma unroll
        for (int j = 0; j < 4; j++) oacc[i][j] = 0.f;

    float4 pk[4], pv[4];
    #pragma unroll
    for (int r = 0; r < 4; r++) {
        pk[r] = *reinterpret_cast<const float4*>(
            Kg + (size_t)(sKey + 16 * r) * QKVC + sD4);
        pv[r] = *reinterpret_cast<const float4*>(
            Vg + (size_t)(sKey + 16 * r) * QKVC + sD4);
    }

    for (int t = 0; t < 16; t++) {
        const int buf = t & 1;
        #pragma unroll
        for (int r = 0; r < 4; r++) {
            const int row = sKey + 16 * r;
            *reinterpret_cast<__half2*>(&sm.K[buf][row][sD4]) =
                __floats2half2_rn(pk[r].x, pk[r].y);
            *reinterpret_cast<__half2*>(&sm.K[buf][row][sD4 + 2]) =
                __floats2half2_rn(pk[r].z, pk[r].w);
            *reinterpret_cast<__half2*>(&sm.V[buf][row][sD4]) =
                __floats2half2_rn(pv[r].x, pv[r].y);
            *reinterpret_cast<__half2*>(&sm.V[buf][row][sD4 + 2]) =
                __floats2half2_rn(pv[r].z, pv[r].w);
        }
        __syncthreads();
        if (t + 1 < 16) {
            #pragma unroll
            for (int r = 0; r < 4; r++) {
                pk[r] = *reinterpret_cast<const float4*>(
                    Kg + (size_t)((t + 1) * 64 + sKey + 16 * r) * QKVC + sD4);
                pv[r] = *reinterpret_cast<const float4*>(
                    Vg + (size_t)((t + 1) * 64 + sKey + 16 * r) * QKVC + sD4);
            }
        }
        float sacc[8][4];
        #pragma unroll
        for (int i = 0; i < 8; i++)
            #pragma unroll
            for (int j = 0; j < 4; j++) sacc[i][j] = 0.f;
        #pragma unroll
        for (int kf = 0; kf < 8; kf++) {
            const uint32_t a0 = *reinterpret_cast<const uint32_t*>(
                &sm.Q[wq * 16 + g][kf * 8 + tg * 2]);
            const uint32_t a1 = *reinterpret_cast<const uint32_t*>(
                &sm.Q[wq * 16 + 8 + g][kf * 8 + tg * 2]);
            #pragma unroll
            for (int nf = 0; nf < 8; nf++) {
                const uint32_t b0 = *reinterpret_cast<const uint32_t*>(
                    &sm.K[buf][nf * 8 + g][kf * 8 + tg * 2]);
                mma_f16k8(sacc[nf], a0, a1, b0);
            }
        }
        const float2 rhv0 = *reinterpret_cast<const float2*>(
            &sm.rh[wq * 16 + g][2 * t]);
        const float2 rhv1 = *reinterpret_cast<const float2*>(
            &sm.rh[wq * 16 + 8 + g][2 * t]);
        uint32_t ap0[8], ap1[8];
        #pragma unroll
        for (int r = 0; r < 2; r++) {
            const float2 rhv = r ? rhv1 : rhv0;
            float vals[8][2];
            float tmax = -INFINITY;
            #pragma unroll
            for (int nf = 0; nf < 8; nf++) {
                const float bias = (nf < 4 ? rhv.x : rhv.y);
                const float2 rwv = rwreg[r][nf & 3];
                float s0 = sacc[nf][2 * r + 0] + bias + rwv.x;
                float s1 = sacc[nf][2 * r + 1] + bias + rwv.y;
                vals[nf][0] = s0; vals[nf][1] = s1;
                tmax = fmaxf(tmax, fmaxf(s0, s1));
            }
            tmax = fmaxf(tmax, __shfl_xor_sync(0xffffffffu, tmax, 1));
            tmax = fmaxf(tmax, __shfl_xor_sync(0xffffffffu, tmax, 2));
            const float nm = fmaxf(m_r[r], tmax);
            float lsum = 0.f;
            #pragma unroll
            for (int nf = 0; nf < 8; nf++) {
                float p0 = __expf(vals[nf][0] - nm);
                float p1 = __expf(vals[nf][1] - nm);
                lsum += p0 + p1;
                uint32_t packed = h2_u32(__floats2half2_rn(p0, p1));
                if (r == 0) ap0[nf] = packed; else ap1[nf] = packed;
            }
            lsum += __shfl_xor_sync(0xffffffffu, lsum, 1);
            lsum += __shfl_xor_sync(0xffffffffu, lsum, 2);
            const float alpha = __expf(m_r[r] - nm);
            m_r[r] = nm;
            l_r[r] = l_r[r] * alpha + lsum;
            #pragma unroll
            for (int nfd = 0; nfd < 8; nfd++) {
                oacc[nfd][2 * r + 0] *= alpha;
                oacc[nfd][2 * r + 1] *= alpha;
            }
        }
        const uint32_t vbase = smem_u32(&sm.V[buf][0][0]);
        #pragma unroll
        for (int kf = 0; kf < 8; kf++) {
            #pragma unroll
            for (int nq = 0; nq < 2; nq++) {
                const int mat = lane >> 3;
                const int nfd = nq * 4 + mat;
                const uint32_t addr = vbase +
                    (uint32_t)((kf * 8 + (lane & 7)) * 144 + nfd * 16);
                uint32_t bf[4];
                ldsm_x4_trans(bf, addr);
                #pragma unroll
                for (int m2 = 0; m2 < 4; m2++)
                    mma_f16k8(oacc[nq * 4 + m2], ap0[kf], ap1[kf], bf[m2]);
            }
        }
    }
    const float li0 = 1.f / l_r[0];
    const float li1 = 1.f / l_r[1];
    #pragma unroll
    for (int nfd = 0; nfd < 8; nfd++) {
        const int d = nfd * 8 + tg * 2;
        float* dst0 = outbuf + ((size_t)b * NTOK + q0) * EMBED + head * HD + d;
        float* dst1 = dst0 + 8 * EMBED;
        *reinterpret_cast<float2*>(dst0) =
            make_float2(oacc[nfd][0] * li0, oacc[nfd][1] * li0);
        *reinterpret_cast<float2*>(dst1) =
            make_float2(oacc[nfd][2] * li1, oacc[nfd][3] * li1);
    }
}

// ---------------- host launcher ----------------
extern "C" void kernel_launch(void* const* d_in, const int* in_sizes, int n_in,
                              void* d_out, int out_size)
{
    const float* x       = (const float*)d_in[0];
    const float* conv_w  = (const float*)d_in[1];
    const float* conv_b  = (const float*)d_in[2];
    const float* pos     = (const float*)d_in[3];
    const float* ln1_w   = (const float*)d_in[4];
    const float* ln1_b   = (const float*)d_in[5];
    const float* qkv_w   = (const float*)d_in[6];
    const float* qkv_b   = (const float*)d_in[7];
    const float* proj_w  = (const float*)d_in[8];
    const float* proj_b  = (const float*)d_in[9];
    const float* rph     = (const float*)d_in[10];
    const float* rpw     = (const float*)d_in[11];
    const float* ln2_w   = (const float*)d_in[12];
    const float* ln2_b   = (const float*)d_in[13];
    const float* fc1_w   = (const float*)d_in[14];
    const float* fc1_b   = (const float*)d_in[15];
    const float* fc2_w   = (const float*)d_in[16];
    const float* fc2_b   = (const float*)d_in[17];
    float* out = (float*)d_out;

    float *h, *ln, *qkv, *attnout, *mlp, *relh, *relw, *col, *wt;
    cudaGetSymbolAddress((void**)&h, g_h);
    cudaGetSymbolAddress((void**)&ln, g_ln);
    cudaGetSymbolAddress((void**)&qkv, g_qkv);
    cudaGetSymbolAddress((void**)&attnout, g_attnout);
    cudaGetSymbolAddress((void**)&mlp, g_mlp);
    cudaGetSymbolAddress((void**)&relh, g_relh);
    cudaGetSymbolAddress((void**)&relw, g_relw);
    cudaGetSymbolAddress((void**)&col, g_col);
    cudaGetSymbolAddress((void**)&wt, g_wt);

    cudaFuncSetAttribute(flash_attn_k,
                         cudaFuncAttributeMaxDynamicSharedMemorySize,
                         (int)sizeof(FlashSmem2));

    transpose768_k<<<(EMBED * EMBED) / 256, 256>>>(conv_w, wt);
    im2col_k<<<(MTOT * EMBED) / 256, 256>>>(x, col);
    mma_gemm<4, 64><<<dim3(EMBED / 128, MTOT / 64), 256>>>(
        MTOT, EMBED, EMBED, col, wt, h, conv_b, pos);

    for (int L = 0; L < DEPTH; L++) {
        layernorm_k<<<MTOT, 256>>>(h, ln1_w + L * EMBED, ln1_b + L * EMBED, ln);
        mma_gemm<1, 128><<<dim3(QKVC / 128, MTOT / 128), 256>>>(
            MTOT, QKVC, EMBED, ln, qkv_w + (size_t)L * EMBED * QKVC, qkv,
            qkv_b + L * QKVC, nullptr);
        rel_tables_k<<<BH * NTOK / 4, 256>>>(qkv, rph + L * RELT * HD,
                                             rpw + L * RELT * HD, relh, relw);
        flash_attn_k<<<dim3(8, BH), 256, sizeof(FlashSmem2)>>>(
            qkv, relh, relw, attnout);
        mma_gemm<2, 64><<<dim3(EMBED / 128, MTOT / 64), 256>>>(
            MTOT, EMBED, EMBED, attnout, proj_w + (size_t)L * EMBED * EMBED, h,
            proj_b + L * EMBED, h);
        layernorm_k<<<MTOT, 256>>>(h, ln2_w + L * EMBED, ln2_b + L * EMBED, ln);
        mma_gemm<3, 128><<<dim3(MLPD / 128, MTOT / 128), 256>>>(
            MTOT, MLPD, EMBED, ln, fc1_w + (size_t)L * EMBED * MLPD, mlp,
            fc1_b + L * MLPD, nullptr);
        float* dst = (L == DEPTH - 1) ? out : h;
        mma_gemm<2, 64><<<dim3(EMBED / 128, MTOT / 64), 256>>>(
            MTOT, EMBED, MLPD, mlp, fc2_w + (size_t)L * MLPD * EMBED, dst,
            fc2_b + L * EMBED, h);
    }
}